// round 4
// baseline (speedup 1.0000x reference)
#include <cuda_runtime.h>

#define B_  8
#define C_  64
#define CQ_ 8
#define H_  128
#define W_  128
#define HW_ (H_*W_)            // 16384
#define NPIX_ (B_*HW_)         // 131072
#define NELEM_ (B_*C_*HW_)     // 8388608
#define NQ_ (B_*CQ_*HW_)       // 1048576

// ---- scratch (device globals; no allocation allowed) ----
__device__ float g_y[NELEM_];
__device__ float g_y2[NELEM_];
__device__ float g_q[NQ_];
__device__ float g_k[NQ_];
__device__ float g_v[NELEM_];
__device__ float g_qT[NQ_];
__device__ float g_kT[NQ_];
__device__ float g_vT[NELEM_];
__device__ float g_accW[NELEM_];
__device__ float g_accHT[NELEM_];
__device__ float g_accH[NELEM_];
__device__ float g_lW[NPIX_];
__device__ float g_lHT[NPIX_];
__device__ float g_lH[NPIX_];

// ---------------- depthwise 3x3 conv, pad 1 ----------------
__global__ void dwconv_kernel(const float* __restrict__ x,
                              const float* __restrict__ wdw,
                              float* __restrict__ y) {
    int idx = blockIdx.x * 256 + threadIdx.x;       // over B*C*H*W
    int w = idx & 127;
    int h = (idx >> 7) & 127;
    int c = (idx >> 14) & 63;
    const float* wp = wdw + c * 9;
    const float* xp = x + (idx & ~16383);           // plane base
    float s = 0.f;
#pragma unroll
    for (int i = 0; i < 3; i++) {
        int hh = h + i - 1;
        if (hh < 0 || hh > 127) continue;
#pragma unroll
        for (int j = 0; j < 3; j++) {
            int ww = w + j - 1;
            if (ww < 0 || ww > 127) continue;
            s += xp[hh * 128 + ww] * wp[i * 3 + j];
        }
    }
    y[idx] = s;
}

// ---------------- per-pixel matvec helper ----------------
__device__ __forceinline__ float dot64(const float* __restrict__ wrow,
                                       const float* __restrict__ yv) {
    const float4* w4 = (const float4*)wrow;
    float s0 = 0.f, s1 = 0.f, s2 = 0.f, s3 = 0.f;
#pragma unroll
    for (int i = 0; i < 16; i += 4) {
        float4 a = w4[i], b = w4[i + 1], c = w4[i + 2], d = w4[i + 3];
        s0 += yv[4*i+0]  * a.x + yv[4*i+1]  * a.y + yv[4*i+2]  * a.z + yv[4*i+3]  * a.w;
        s1 += yv[4*i+4]  * b.x + yv[4*i+5]  * b.y + yv[4*i+6]  * b.z + yv[4*i+7]  * b.w;
        s2 += yv[4*i+8]  * c.x + yv[4*i+9]  * c.y + yv[4*i+10] * c.z + yv[4*i+11] * c.w;
        s3 += yv[4*i+12] * d.x + yv[4*i+13] * d.y + yv[4*i+14] * d.z + yv[4*i+15] * d.w;
    }
    return (s0 + s1) + (s2 + s3);
}

// ---------------- q,k,v projection ----------------
__global__ void __launch_bounds__(256) qkv_kernel(
    const float* __restrict__ in, const float* __restrict__ wq,
    const float* __restrict__ wk, const float* __restrict__ wv,
    float* __restrict__ q, float* __restrict__ k, float* __restrict__ v) {
    __shared__ float ws[80 * 64];                   // 20 KB: q(8) k(8) v(64) rows
    int tid = threadIdx.x;
    for (int i = tid; i < 512; i += 256) { ws[i] = wq[i]; ws[512 + i] = wk[i]; }
    for (int i = tid; i < 4096; i += 256) ws[1024 + i] = wv[i];
    __syncthreads();

    int pix = blockIdx.x * 256 + tid;
    int b = pix >> 14, hw = pix & 16383;
    const float* ip = in + b * C_ * HW_ + hw;
    float yv[64];
#pragma unroll
    for (int c = 0; c < 64; c++) yv[c] = ip[c * HW_];

#pragma unroll 1
    for (int o = 0; o < 8; o++) {
        q[(b * 8 + o) * HW_ + hw] = dot64(&ws[o * 64], yv);
        k[(b * 8 + o) * HW_ + hw] = dot64(&ws[512 + o * 64], yv);
    }
#pragma unroll 1
    for (int o = 0; o < 64; o++)
        v[(b * 64 + o) * HW_ + hw] = dot64(&ws[1024 + o * 64], yv);
}

// ---------------- batched 128x128 plane transpose ----------------
__global__ void transpose_kernel(const float* __restrict__ in, float* __restrict__ out) {
    __shared__ float tile[32][33];
    int p = blockIdx.z;
    const float* ip = in + p * HW_;
    float* op = out + p * HW_;
    int tx = threadIdx.x, ty = threadIdx.y;
    int i0 = blockIdx.y * 32, j0 = blockIdx.x * 32;
#pragma unroll
    for (int r = 0; r < 4; r++)
        tile[ty + 8 * r][tx] = ip[(i0 + ty + 8 * r) * 128 + j0 + tx];
    __syncthreads();
#pragma unroll
    for (int r = 0; r < 4; r++)
        op[(j0 + ty + 8 * r) * 128 + i0 + tx] = tile[tx][ty + 8 * r];
}

// ---------------- directional attention (one row per block) ----------------
// For each pixel in row r: l = sum_t exp(e_t), acc[c] = sum_t exp(e_t) * v[c][t]
// mask_diag: zero the t==tid term (H-direction diagonal mask, run on transposed data)
__global__ void __launch_bounds__(128) attn_kernel(
    const float* __restrict__ q, const float* __restrict__ k,
    const float* __restrict__ v, float* __restrict__ acc_out,
    float* __restrict__ l_out, int mask_diag) {
    __shared__ float skT[128][8];    // [t][d]
    __shared__ float svT[128][68];   // [t][c], pad 68 keeps 16B alignment
    int bh = blockIdx.x;
    int b = bh >> 7, r = bh & 127;
    int tid = threadIdx.x;

    const float* kb = k + (b * CQ_) * HW_ + r * W_;
#pragma unroll
    for (int d = 0; d < 8; d++) skT[tid][d] = kb[d * HW_ + tid];
    const float* vb = v + (b * C_) * HW_ + r * W_;
#pragma unroll
    for (int c = 0; c < 64; c++) svT[tid][c] = vb[c * HW_ + tid];

    float qr[8];
    const float* qb = q + (b * CQ_) * HW_ + r * W_ + tid;
#pragma unroll
    for (int d = 0; d < 8; d++) qr[d] = qb[d * HW_];
    __syncthreads();

    float l = 0.f;
    float acc[64];
#pragma unroll
    for (int c = 0; c < 64; c++) acc[c] = 0.f;

#pragma unroll 1
    for (int t = 0; t < 128; t++) {
        const float4* kr = (const float4*)skT[t];
        float4 k0 = kr[0], k1 = kr[1];
        float e = qr[0]*k0.x + qr[1]*k0.y + qr[2]*k0.z + qr[3]*k0.w
                + qr[4]*k1.x + qr[5]*k1.y + qr[6]*k1.z + qr[7]*k1.w;
        float p = __expf(e);
        if (mask_diag && t == tid) p = 0.f;   // diag -> weight exactly 0
        l += p;
        const float4* vr = (const float4*)svT[t];
#pragma unroll
        for (int i = 0; i < 16; i++) {
            float4 vv = vr[i];
            acc[4*i+0] += p * vv.x;
            acc[4*i+1] += p * vv.y;
            acc[4*i+2] += p * vv.z;
            acc[4*i+3] += p * vv.w;
        }
    }

    float* ob = acc_out + (b * C_) * HW_ + r * W_ + tid;
#pragma unroll
    for (int c = 0; c < 64; c++) ob[c * HW_] = acc[c];
    l_out[b * HW_ + r * W_ + tid] = l;
}

// ---------------- combine: out = y + gamma*(accH+accW)/(lH+lW) ----------------
__global__ void combine_kernel(
    const float* __restrict__ yin, const float* __restrict__ accH,
    const float* __restrict__ accW, const float* __restrict__ lH,
    const float* __restrict__ lW, const float* __restrict__ gamma,
    float* __restrict__ out) {
    int i = blockIdx.x * 256 + threadIdx.x;   // float4 index
    int e = i * 4;
    int pix = (e >> 20) * HW_ + (e & 16383);  // b*HW + hw (4 elems share plane row)
    float g = *gamma;
    float4 aH = ((const float4*)accH)[i];
    float4 aW = ((const float4*)accW)[i];
    float4 yy = ((const float4*)yin)[i];
    float4 lh = *(const float4*)&lH[pix];
    float4 lw = *(const float4*)&lW[pix];
    float4 o;
    o.x = yy.x + g * (aH.x + aW.x) / (lh.x + lw.x);
    o.y = yy.y + g * (aH.y + aW.y) / (lh.y + lw.y);
    o.z = yy.z + g * (aH.z + aW.z) / (lh.z + lw.z);
    o.w = yy.w + g * (aH.w + aW.w) / (lh.w + lw.w);
    ((float4*)out)[i] = o;
}

// ---------------- pointwise 1x1 conv ----------------
__global__ void __launch_bounds__(256) pw_kernel(
    const float* __restrict__ in, const float* __restrict__ wpw,
    float* __restrict__ out) {
    __shared__ float ws[4096];
    int tid = threadIdx.x;
    for (int i = tid; i < 4096; i += 256) ws[i] = wpw[i];
    __syncthreads();
    int pix = blockIdx.x * 256 + tid;
    int b = pix >> 14, hw = pix & 16383;
    const float* ip = in + b * C_ * HW_ + hw;
    float yv[64];
#pragma unroll
    for (int c = 0; c < 64; c++) yv[c] = ip[c * HW_];
#pragma unroll 1
    for (int o = 0; o < 64; o++)
        out[(b * 64 + o) * HW_ + hw] = dot64(&ws[o * 64], yv);
}

extern "C" void kernel_launch(void* const* d_in, const int* in_sizes, int n_in,
                              void* d_out, int out_size) {
    const float* x    = (const float*)d_in[0];
    const float* w_dw = (const float*)d_in[1];
    const float* wq   = (const float*)d_in[2];
    const float* wk   = (const float*)d_in[3];
    const float* wv   = (const float*)d_in[4];
    const float* gam  = (const float*)d_in[5];
    const float* w_pw = (const float*)d_in[6];
    float* out = (float*)d_out;

    float *y, *y2, *q, *k, *v, *qT, *kT, *vT, *accW, *accHT, *accH, *lW, *lHT, *lH;
    cudaGetSymbolAddress((void**)&y, g_y);
    cudaGetSymbolAddress((void**)&y2, g_y2);
    cudaGetSymbolAddress((void**)&q, g_q);
    cudaGetSymbolAddress((void**)&k, g_k);
    cudaGetSymbolAddress((void**)&v, g_v);
    cudaGetSymbolAddress((void**)&qT, g_qT);
    cudaGetSymbolAddress((void**)&kT, g_kT);
    cudaGetSymbolAddress((void**)&vT, g_vT);
    cudaGetSymbolAddress((void**)&accW, g_accW);
    cudaGetSymbolAddress((void**)&accHT, g_accHT);
    cudaGetSymbolAddress((void**)&accH, g_accH);
    cudaGetSymbolAddress((void**)&lW, g_lW);
    cudaGetSymbolAddress((void**)&lHT, g_lHT);
    cudaGetSymbolAddress((void**)&lH, g_lH);

    dwconv_kernel<<<NELEM_ / 256, 256>>>(x, w_dw, y);

    const float* cin = y;
    float* cout = y2;
    for (int pass = 0; pass < 2; pass++) {
        qkv_kernel<<<NPIX_ / 256, 256>>>(cin, wq, wk, wv, q, k, v);
        transpose_kernel<<<dim3(4, 4, B_ * CQ_), dim3(32, 8)>>>(q, qT);
        transpose_kernel<<<dim3(4, 4, B_ * CQ_), dim3(32, 8)>>>(k, kT);
        transpose_kernel<<<dim3(4, 4, B_ * C_),  dim3(32, 8)>>>(v, vT);
        // W-direction (rows, no mask)
        attn_kernel<<<B_ * H_, 128>>>(q, k, v, accW, lW, 0);
        // H-direction (rows of transposed image, diagonal mask)
        attn_kernel<<<B_ * W_, 128>>>(qT, kT, vT, accHT, lHT, 1);
        transpose_kernel<<<dim3(4, 4, B_ * C_), dim3(32, 8)>>>(accHT, accH);
        transpose_kernel<<<dim3(4, 4, B_),      dim3(32, 8)>>>(lHT, lH);
        combine_kernel<<<NELEM_ / 1024, 256>>>(cin, accH, accW, lH, lW, gam, cout);
        const float* t = cin; cin = cout; cout = (float*)t;
    }

    pw_kernel<<<NPIX_ / 256, 256>>>(cin, w_pw, out);
}

// round 5
// speedup vs baseline: 1.1099x; 1.1099x over previous
#include <cuda_runtime.h>

#define B_  8
#define C_  64
#define CQ_ 8
#define H_  128
#define W_  128
#define HW_ (H_*W_)            // 16384
#define NPIX_ (B_*HW_)         // 131072
#define NELEM_ (B_*C_*HW_)     // 8388608
#define NQ_ (B_*CQ_*HW_)       // 1048576

typedef unsigned long long u64;

// ---- packed fp32x2 helpers (SASS FFMA2 path; exact fp32 per lane) ----
__device__ __forceinline__ u64 fma2(u64 a, u64 b, u64 c) {
    u64 d; asm("fma.rn.f32x2 %0, %1, %2, %3;" : "=l"(d) : "l"(a), "l"(b), "l"(c));
    return d;
}
__device__ __forceinline__ u64 mul2(u64 a, u64 b) {
    u64 d; asm("mul.rn.f32x2 %0, %1, %2;" : "=l"(d) : "l"(a), "l"(b));
    return d;
}
__device__ __forceinline__ u64 add2(u64 a, u64 b) {
    u64 d; asm("add.rn.f32x2 %0, %1, %2;" : "=l"(d) : "l"(a), "l"(b));
    return d;
}
__device__ __forceinline__ u64 pack2(float lo, float hi) {
    u64 d; asm("mov.b64 %0, {%1, %2};" : "=l"(d) : "f"(lo), "f"(hi));
    return d;
}
__device__ __forceinline__ void unpack2(u64 a, float& lo, float& hi) {
    asm("mov.b64 {%0, %1}, %2;" : "=f"(lo), "=f"(hi) : "l"(a));
}

// ---- scratch (device globals; no allocation allowed) ----
__device__ float g_y[NELEM_];
__device__ float g_y2[NELEM_];
__device__ float g_q[NQ_];
__device__ float g_k[NQ_];
__device__ float g_v[NELEM_];
__device__ float g_qT[NQ_];
__device__ float g_kT[NQ_];
__device__ float g_vT[NELEM_];
__device__ float g_accW[NELEM_];
__device__ float g_accHT[NELEM_];
__device__ float g_accH[NELEM_];
__device__ float g_lW[NPIX_];
__device__ float g_lHT[NPIX_];
__device__ float g_lH[NPIX_];

// ---------------- depthwise 3x3 conv, pad 1 ----------------
__global__ void dwconv_kernel(const float* __restrict__ x,
                              const float* __restrict__ wdw,
                              float* __restrict__ y) {
    int idx = blockIdx.x * 256 + threadIdx.x;       // over B*C*H*W
    int w = idx & 127;
    int h = (idx >> 7) & 127;
    int c = (idx >> 14) & 63;
    const float* wp = wdw + c * 9;
    const float* xp = x + (idx & ~16383);           // plane base
    float s = 0.f;
#pragma unroll
    for (int i = 0; i < 3; i++) {
        int hh = h + i - 1;
        if (hh < 0 || hh > 127) continue;
#pragma unroll
        for (int j = 0; j < 3; j++) {
            int ww = w + j - 1;
            if (ww < 0 || ww > 127) continue;
            s += xp[hh * 128 + ww] * wp[i * 3 + j];
        }
    }
    y[idx] = s;
}

// ---------------- packed per-pixel matvec: sum_c w[c]*y[c], c=0..63 ----------------
// wrow: 64 consecutive floats (16B aligned, smem). yp: 32 packed pairs (ch 2i,2i+1).
__device__ __forceinline__ float dot64p(const float* __restrict__ wrow,
                                        const u64* __restrict__ yp) {
    const ulonglong2* w2 = (const ulonglong2*)wrow;
    u64 s0 = 0ull, s1 = 0ull, s2 = 0ull, s3 = 0ull;
#pragma unroll
    for (int i = 0; i < 8; i++) {
        ulonglong2 a = w2[2 * i], b = w2[2 * i + 1];
        s0 = fma2(yp[4 * i + 0], a.x, s0);
        s1 = fma2(yp[4 * i + 1], a.y, s1);
        s2 = fma2(yp[4 * i + 2], b.x, s2);
        s3 = fma2(yp[4 * i + 3], b.y, s3);
    }
    u64 s = add2(add2(s0, s1), add2(s2, s3));
    float lo, hi; unpack2(s, lo, hi);
    return lo + hi;
}

// ---------------- q,k,v projection ----------------
__global__ void __launch_bounds__(256) qkv_kernel(
    const float* __restrict__ in, const float* __restrict__ wq,
    const float* __restrict__ wk, const float* __restrict__ wv,
    float* __restrict__ q, float* __restrict__ k, float* __restrict__ v) {
    __shared__ float ws[80 * 64];                   // 20 KB: q(8) k(8) v(64) rows
    int tid = threadIdx.x;
    for (int i = tid; i < 512; i += 256) { ws[i] = wq[i]; ws[512 + i] = wk[i]; }
    for (int i = tid; i < 4096; i += 256) ws[1024 + i] = wv[i];
    __syncthreads();

    int pix = blockIdx.x * 256 + tid;
    int b = pix >> 14, hw = pix & 16383;
    const float* ip = in + b * C_ * HW_ + hw;
    u64 yp[32];
#pragma unroll
    for (int c = 0; c < 32; c++)
        yp[c] = pack2(ip[(2 * c) * HW_], ip[(2 * c + 1) * HW_]);

#pragma unroll 1
    for (int o = 0; o < 8; o++) {
        q[(b * 8 + o) * HW_ + hw] = dot64p(&ws[o * 64], yp);
        k[(b * 8 + o) * HW_ + hw] = dot64p(&ws[512 + o * 64], yp);
    }
#pragma unroll 1
    for (int o = 0; o < 64; o++)
        v[(b * 64 + o) * HW_ + hw] = dot64p(&ws[1024 + o * 64], yp);
}

// ---------------- batched 128x128 plane transpose ----------------
__global__ void transpose_kernel(const float* __restrict__ in, float* __restrict__ out) {
    __shared__ float tile[32][33];
    int p = blockIdx.z;
    const float* ip = in + p * HW_;
    float* op = out + p * HW_;
    int tx = threadIdx.x, ty = threadIdx.y;
    int i0 = blockIdx.y * 32, j0 = blockIdx.x * 32;
#pragma unroll
    for (int r = 0; r < 4; r++)
        tile[ty + 8 * r][tx] = ip[(i0 + ty + 8 * r) * 128 + j0 + tx];
    __syncthreads();
#pragma unroll
    for (int r = 0; r < 4; r++)
        op[(j0 + ty + 8 * r) * 128 + i0 + tx] = tile[tx][ty + 8 * r];
}

// ---------------- directional attention (one row per block) ----------------
// For each pixel in row r: l = sum_t exp(e_t), acc[c] = sum_t exp(e_t) * v[c][t]
// mask_diag: zero the t==tid term (H-direction diagonal mask, run on transposed data)
__global__ void __launch_bounds__(128) attn_kernel(
    const float* __restrict__ q, const float* __restrict__ k,
    const float* __restrict__ v, float* __restrict__ acc_out,
    float* __restrict__ l_out, int mask_diag) {
    __shared__ float skT[128][8];    // [t][d]
    __shared__ float svT[128][68];   // [t][c], pad 68 keeps 16B row alignment
    int bh = blockIdx.x;
    int b = bh >> 7, r = bh & 127;
    int tid = threadIdx.x;

    const float* kb = k + (b * CQ_) * HW_ + r * W_;
#pragma unroll
    for (int d = 0; d < 8; d++) skT[tid][d] = kb[d * HW_ + tid];
    const float* vb = v + (b * C_) * HW_ + r * W_;
#pragma unroll
    for (int c = 0; c < 64; c++) svT[tid][c] = vb[c * HW_ + tid];

    u64 qp[4];
    {
        const float* qb = q + (b * CQ_) * HW_ + r * W_ + tid;
#pragma unroll
        for (int d = 0; d < 4; d++)
            qp[d] = pack2(qb[(2 * d) * HW_], qb[(2 * d + 1) * HW_]);
    }
    __syncthreads();

    float l = 0.f;
    u64 acc[32];
#pragma unroll
    for (int i = 0; i < 32; i++) acc[i] = 0ull;

#pragma unroll 1
    for (int t = 0; t < 128; t++) {
        const ulonglong2* kr = (const ulonglong2*)skT[t];
        ulonglong2 k01 = kr[0], k23 = kr[1];
        u64 s = mul2(qp[0], k01.x);
        s = fma2(qp[1], k01.y, s);
        s = fma2(qp[2], k23.x, s);
        s = fma2(qp[3], k23.y, s);
        float lo, hi; unpack2(s, lo, hi);
        float e = lo + hi;
        float p = __expf(e);
        if (mask_diag && t == tid) p = 0.f;   // diag -> weight exactly 0
        l += p;
        u64 pp = pack2(p, p);
        const ulonglong2* vr = (const ulonglong2*)svT[t];
#pragma unroll
        for (int i = 0; i < 16; i++) {
            ulonglong2 vv = vr[i];
            acc[2 * i + 0] = fma2(pp, vv.x, acc[2 * i + 0]);
            acc[2 * i + 1] = fma2(pp, vv.y, acc[2 * i + 1]);
        }
    }

    float* ob = acc_out + (b * C_) * HW_ + r * W_ + tid;
#pragma unroll
    for (int i = 0; i < 32; i++) {
        float a0, a1; unpack2(acc[i], a0, a1);
        ob[(2 * i) * HW_]     = a0;
        ob[(2 * i + 1) * HW_] = a1;
    }
    l_out[b * HW_ + r * W_ + tid] = l;
}

// ---------------- combine: out = y + gamma*(accH+accW)/(lH+lW) ----------------
__global__ void combine_kernel(
    const float* __restrict__ yin, const float* __restrict__ accH,
    const float* __restrict__ accW, const float* __restrict__ lH,
    const float* __restrict__ lW, const float* __restrict__ gamma,
    float* __restrict__ out) {
    int i = blockIdx.x * 256 + threadIdx.x;   // float4 index
    int e = i * 4;
    int pix = (e >> 20) * HW_ + (e & 16383);  // b*HW + hw (4 elems share plane row)
    float g = *gamma;
    float4 aH = ((const float4*)accH)[i];
    float4 aW = ((const float4*)accW)[i];
    float4 yy = ((const float4*)yin)[i];
    float4 lh = *(const float4*)&lH[pix];
    float4 lw = *(const float4*)&lW[pix];
    float4 o;
    o.x = yy.x + g * (aH.x + aW.x) / (lh.x + lw.x);
    o.y = yy.y + g * (aH.y + aW.y) / (lh.y + lw.y);
    o.z = yy.z + g * (aH.z + aW.z) / (lh.z + lw.z);
    o.w = yy.w + g * (aH.w + aW.w) / (lh.w + lw.w);
    ((float4*)out)[i] = o;
}

// ---------------- pointwise 1x1 conv ----------------
__global__ void __launch_bounds__(256) pw_kernel(
    const float* __restrict__ in, const float* __restrict__ wpw,
    float* __restrict__ out) {
    __shared__ float ws[4096];
    int tid = threadIdx.x;
    for (int i = tid; i < 4096; i += 256) ws[i] = wpw[i];
    __syncthreads();
    int pix = blockIdx.x * 256 + tid;
    int b = pix >> 14, hw = pix & 16383;
    const float* ip = in + b * C_ * HW_ + hw;
    u64 yp[32];
#pragma unroll
    for (int c = 0; c < 32; c++)
        yp[c] = pack2(ip[(2 * c) * HW_], ip[(2 * c + 1) * HW_]);
#pragma unroll 1
    for (int o = 0; o < 64; o++)
        out[(b * 64 + o) * HW_ + hw] = dot64p(&ws[o * 64], yp);
}

extern "C" void kernel_launch(void* const* d_in, const int* in_sizes, int n_in,
                              void* d_out, int out_size) {
    const float* x    = (const float*)d_in[0];
    const float* w_dw = (const float*)d_in[1];
    const float* wq   = (const float*)d_in[2];
    const float* wk   = (const float*)d_in[3];
    const float* wv   = (const float*)d_in[4];
    const float* gam  = (const float*)d_in[5];
    const float* w_pw = (const float*)d_in[6];
    float* out = (float*)d_out;

    float *y, *y2, *q, *k, *v, *qT, *kT, *vT, *accW, *accHT, *accH, *lW, *lHT, *lH;
    cudaGetSymbolAddress((void**)&y, g_y);
    cudaGetSymbolAddress((void**)&y2, g_y2);
    cudaGetSymbolAddress((void**)&q, g_q);
    cudaGetSymbolAddress((void**)&k, g_k);
    cudaGetSymbolAddress((void**)&v, g_v);
    cudaGetSymbolAddress((void**)&qT, g_qT);
    cudaGetSymbolAddress((void**)&kT, g_kT);
    cudaGetSymbolAddress((void**)&vT, g_vT);
    cudaGetSymbolAddress((void**)&accW, g_accW);
    cudaGetSymbolAddress((void**)&accHT, g_accHT);
    cudaGetSymbolAddress((void**)&accH, g_accH);
    cudaGetSymbolAddress((void**)&lW, g_lW);
    cudaGetSymbolAddress((void**)&lHT, g_lHT);
    cudaGetSymbolAddress((void**)&lH, g_lH);

    dwconv_kernel<<<NELEM_ / 256, 256>>>(x, w_dw, y);

    const float* cin = y;
    float* cout = y2;
    for (int pass = 0; pass < 2; pass++) {
        qkv_kernel<<<NPIX_ / 256, 256>>>(cin, wq, wk, wv, q, k, v);
        transpose_kernel<<<dim3(4, 4, B_ * CQ_), dim3(32, 8)>>>(q, qT);
        transpose_kernel<<<dim3(4, 4, B_ * CQ_), dim3(32, 8)>>>(k, kT);
        transpose_kernel<<<dim3(4, 4, B_ * C_),  dim3(32, 8)>>>(v, vT);
        // W-direction (rows, no mask)
        attn_kernel<<<B_ * H_, 128>>>(q, k, v, accW, lW, 0);
        // H-direction (rows of transposed image, diagonal mask)
        attn_kernel<<<B_ * W_, 128>>>(qT, kT, vT, accHT, lHT, 1);
        transpose_kernel<<<dim3(4, 4, B_ * C_), dim3(32, 8)>>>(accHT, accH);
        transpose_kernel<<<dim3(4, 4, B_),      dim3(32, 8)>>>(lHT, lH);
        combine_kernel<<<NELEM_ / 1024, 256>>>(cin, accH, accW, lH, lW, gam, cout);
        const float* t = cin; cin = cout; cout = (float*)t;
    }

    pw_kernel<<<NPIX_ / 256, 256>>>(cin, w_pw, out);
}

// round 8
// speedup vs baseline: 1.4945x; 1.3466x over previous
#include <cuda_runtime.h>
#include <cstdint>

#define B_  8
#define C_  64
#define CQ_ 8
#define H_  128
#define W_  128
#define HW_ (H_*W_)            // 16384
#define NPIX_ (B_*HW_)         // 131072
#define NELEM_ (B_*C_*HW_)     // 8388608
#define NQ_ (B_*CQ_*HW_)       // 1048576

typedef unsigned long long u64;

// ---- packed fp32x2 helpers (SASS FFMA2 path; exact fp32 per lane) ----
__device__ __forceinline__ u64 fma2(u64 a, u64 b, u64 c) {
    u64 d; asm("fma.rn.f32x2 %0, %1, %2, %3;" : "=l"(d) : "l"(a), "l"(b), "l"(c));
    return d;
}
__device__ __forceinline__ u64 mul2(u64 a, u64 b) {
    u64 d; asm("mul.rn.f32x2 %0, %1, %2;" : "=l"(d) : "l"(a), "l"(b));
    return d;
}
__device__ __forceinline__ u64 add2(u64 a, u64 b) {
    u64 d; asm("add.rn.f32x2 %0, %1, %2;" : "=l"(d) : "l"(a), "l"(b));
    return d;
}
__device__ __forceinline__ u64 pack2(float lo, float hi) {
    u64 d; asm("mov.b64 %0, {%1, %2};" : "=l"(d) : "f"(lo), "f"(hi));
    return d;
}
__device__ __forceinline__ void unpack2(u64 a, float& lo, float& hi) {
    asm("mov.b64 {%0, %1}, %2;" : "=f"(lo), "=f"(hi) : "l"(a));
}

// ---- tf32 helpers ----
__device__ __forceinline__ uint32_t tf32r(float f) {
    uint32_t r; asm("cvt.rna.tf32.f32 %0, %1;" : "=r"(r) : "f"(f));
    return r;
}
__device__ __forceinline__ float tf32f(float f) {
    return __uint_as_float(tf32r(f));
}
__device__ __forceinline__ void mma_tf32(float* d,
    uint32_t a0, uint32_t a1, uint32_t a2, uint32_t a3,
    uint32_t b0, uint32_t b1) {
    asm("mma.sync.aligned.m16n8k8.row.col.f32.tf32.tf32.f32 "
        "{%0,%1,%2,%3}, {%4,%5,%6,%7}, {%8,%9}, {%0,%1,%2,%3};"
        : "+f"(d[0]), "+f"(d[1]), "+f"(d[2]), "+f"(d[3])
        : "r"(a0), "r"(a1), "r"(a2), "r"(a3), "r"(b0), "r"(b1));
}

// ---- scratch (device globals; no allocation allowed) ----
__device__ float g_y[NELEM_];
__device__ float g_y2[NELEM_];
__device__ float g_q[NQ_];
__device__ float g_k[NQ_];
__device__ float g_v[NELEM_];
__device__ float g_qT[NQ_];
__device__ float g_kT[NQ_];
__device__ float g_vT[NELEM_];
__device__ float g_accW[NELEM_];
__device__ float g_accHT[NELEM_];
__device__ float g_lW[NPIX_];
__device__ float g_lHT[NPIX_];

// ---------------- depthwise 3x3 conv, pad 1 ----------------
__global__ void dwconv_kernel(const float* __restrict__ x,
                              const float* __restrict__ wdw,
                              float* __restrict__ y) {
    int idx = blockIdx.x * 256 + threadIdx.x;       // over B*C*H*W
    int w = idx & 127;
    int h = (idx >> 7) & 127;
    int c = (idx >> 14) & 63;
    const float* wp = wdw + c * 9;
    const float* xp = x + (idx & ~16383);           // plane base
    float s = 0.f;
#pragma unroll
    for (int i = 0; i < 3; i++) {
        int hh = h + i - 1;
        if (hh < 0 || hh > 127) continue;
#pragma unroll
        for (int j = 0; j < 3; j++) {
            int ww = w + j - 1;
            if (ww < 0 || ww > 127) continue;
            s += xp[hh * 128 + ww] * wp[i * 3 + j];
        }
    }
    y[idx] = s;
}

// ---------------- packed per-pixel matvec ----------------
__device__ __forceinline__ float dot64p(const float* __restrict__ wrow,
                                        const u64* __restrict__ yp) {
    const ulonglong2* w2 = (const ulonglong2*)wrow;
    u64 s0 = 0ull, s1 = 0ull, s2 = 0ull, s3 = 0ull;
#pragma unroll
    for (int i = 0; i < 8; i++) {
        ulonglong2 a = w2[2 * i], b = w2[2 * i + 1];
        s0 = fma2(yp[4 * i + 0], a.x, s0);
        s1 = fma2(yp[4 * i + 1], a.y, s1);
        s2 = fma2(yp[4 * i + 2], b.x, s2);
        s3 = fma2(yp[4 * i + 3], b.y, s3);
    }
    u64 s = add2(add2(s0, s1), add2(s2, s3));
    float lo, hi; unpack2(s, lo, hi);
    return lo + hi;
}

// ---------------- q,k,v projection ----------------
__global__ void __launch_bounds__(256) qkv_kernel(
    const float* __restrict__ in, const float* __restrict__ wq,
    const float* __restrict__ wk, const float* __restrict__ wv,
    float* __restrict__ q, float* __restrict__ k, float* __restrict__ v) {
    __shared__ float ws[80 * 64];
    int tid = threadIdx.x;
    for (int i = tid; i < 512; i += 256) { ws[i] = wq[i]; ws[512 + i] = wk[i]; }
    for (int i = tid; i < 4096; i += 256) ws[1024 + i] = wv[i];
    __syncthreads();

    int pix = blockIdx.x * 256 + tid;
    int b = pix >> 14, hw = pix & 16383;
    const float* ip = in + b * C_ * HW_ + hw;
    u64 yp[32];
#pragma unroll
    for (int c = 0; c < 32; c++)
        yp[c] = pack2(ip[(2 * c) * HW_], ip[(2 * c + 1) * HW_]);

#pragma unroll 1
    for (int o = 0; o < 8; o++) {
        q[(b * 8 + o) * HW_ + hw] = dot64p(&ws[o * 64], yp);
        k[(b * 8 + o) * HW_ + hw] = dot64p(&ws[512 + o * 64], yp);
    }
#pragma unroll 1
    for (int o = 0; o < 64; o++)
        v[(b * 64 + o) * HW_ + hw] = dot64p(&ws[1024 + o * 64], yp);
}

// ---------------- batched 128x128 plane transpose ----------------
__global__ void transpose_kernel(const float* __restrict__ in, float* __restrict__ out) {
    __shared__ float tile[32][33];
    int p = blockIdx.z;
    const float* ip = in + p * HW_;
    float* op = out + p * HW_;
    int tx = threadIdx.x, ty = threadIdx.y;
    int i0 = blockIdx.y * 32, j0 = blockIdx.x * 32;
#pragma unroll
    for (int r = 0; r < 4; r++)
        tile[ty + 8 * r][tx] = ip[(i0 + ty + 8 * r) * 128 + j0 + tx];
    __syncthreads();
#pragma unroll
    for (int r = 0; r < 4; r++)
        op[(j0 + ty + 8 * r) * 128 + i0 + tx] = tile[tx][ty + 8 * r];
}

// ---------------- directional attention (one row per block) ----------------
// Phase 1 (scalar, fp32): e_t = q.k_t, p = exp(e), l = sum p; P -> smem (tf32)
// Phase 2 (tensor, tf32 mma): out[128q,64c] = P[128,128] * Vt[128,64]
// smem layout (dynamic): skT[128][8] | svT[128][72] | sP[128][132]
#define ATTN_SMEM_FLOATS (128*8 + 128*72 + 128*132)   // 27136 floats = 108544 B
__global__ void __launch_bounds__(128) attn_kernel(
    const float* __restrict__ q, const float* __restrict__ k,
    const float* __restrict__ v, float* __restrict__ acc_out,
    float* __restrict__ l_out, int mask_diag) {
    extern __shared__ float smem[];
    float (*skT)[8]   = (float(*)[8])smem;
    float (*svT)[72]  = (float(*)[72])(smem + 128 * 8);
    float (*sP)[132]  = (float(*)[132])(smem + 128 * 8 + 128 * 72);

    int bh = blockIdx.x;
    int b = bh >> 7, r = bh & 127;
    int tid = threadIdx.x;

    // load K row (t = tid): skT[t][d]
    const float* kb = k + (b * CQ_) * HW_ + r * W_;
#pragma unroll
    for (int d = 0; d < 8; d++) skT[tid][d] = kb[d * HW_ + tid];

    // load V row transposed, tf32-rounded: svT[t][c]
    const float* vb = v + (b * C_) * HW_ + r * W_;
#pragma unroll
    for (int c4 = 0; c4 < 16; c4++) {
        float4 vv;
        vv.x = tf32f(vb[(4 * c4 + 0) * HW_ + tid]);
        vv.y = tf32f(vb[(4 * c4 + 1) * HW_ + tid]);
        vv.z = tf32f(vb[(4 * c4 + 2) * HW_ + tid]);
        vv.w = tf32f(vb[(4 * c4 + 3) * HW_ + tid]);
        *(float4*)&svT[tid][4 * c4] = vv;
    }

    // q for this thread's query pixel (packed pairs)
    u64 qp[4];
    {
        const float* qb = q + (b * CQ_) * HW_ + r * W_ + tid;
#pragma unroll
        for (int d = 0; d < 4; d++)
            qp[d] = pack2(qb[(2 * d) * HW_], qb[(2 * d + 1) * HW_]);
    }
    __syncthreads();

    // ---- Phase 1: scalar logits (fp32), write P (tf32 bits) ----
    float l = 0.f;
#pragma unroll 1
    for (int t = 0; t < 128; t += 4) {
        float4 pv;
#pragma unroll
        for (int j = 0; j < 4; j++) {
            const ulonglong2* kr = (const ulonglong2*)&skT[t + j][0];
            ulonglong2 k01 = kr[0], k23 = kr[1];
            u64 s = mul2(qp[0], k01.x);
            s = fma2(qp[1], k01.y, s);
            s = fma2(qp[2], k23.x, s);
            s = fma2(qp[3], k23.y, s);
            float lo, hi; unpack2(s, lo, hi);
            float p = __expf(lo + hi);
            if (mask_diag && (t + j) == tid) p = 0.f;   // diag -> weight 0
            l += p;
            ((uint32_t*)&pv)[j] = tf32r(p);
        }
        *(float4*)&sP[tid][t] = pv;
    }
    l_out[b * HW_ + r * W_ + tid] = l;
    __syncthreads();

    // ---- Phase 2: Out = P * Vt via tf32 mma ----
    int lane = tid & 31, wrp = tid >> 5;
    int gid = lane >> 2, tig = lane & 3;
    float acc[2][8][4];
#pragma unroll
    for (int mt = 0; mt < 2; mt++)
#pragma unroll
        for (int n = 0; n < 8; n++)
#pragma unroll
            for (int i = 0; i < 4; i++) acc[mt][n][i] = 0.f;

#pragma unroll 1
    for (int kt = 0; kt < 16; kt++) {
        int k0 = kt * 8;
        uint32_t bf0[8], bf1[8];
#pragma unroll
        for (int n = 0; n < 8; n++) {
            bf0[n] = __float_as_uint(svT[k0 + tig][n * 8 + gid]);
            bf1[n] = __float_as_uint(svT[k0 + tig + 4][n * 8 + gid]);
        }
#pragma unroll
        for (int mt = 0; mt < 2; mt++) {
            int q0 = wrp * 32 + mt * 16;
            uint32_t a0 = __float_as_uint(sP[q0 + gid][k0 + tig]);
            uint32_t a1 = __float_as_uint(sP[q0 + 8 + gid][k0 + tig]);
            uint32_t a2 = __float_as_uint(sP[q0 + gid][k0 + 4 + tig]);
            uint32_t a3 = __float_as_uint(sP[q0 + 8 + gid][k0 + 4 + tig]);
#pragma unroll
            for (int n = 0; n < 8; n++)
                mma_tf32(acc[mt][n], a0, a1, a2, a3, bf0[n], bf1[n]);
        }
    }

    // epilogue: C frag (m16n8): rows q0+gid / +8, cols 2*tig / +1
    float* ob = acc_out + (b * C_) * HW_ + r * W_;
#pragma unroll
    for (int mt = 0; mt < 2; mt++) {
        int qq = wrp * 32 + mt * 16 + gid;
#pragma unroll
        for (int n = 0; n < 8; n++) {
            int cc = n * 8 + 2 * tig;
            ob[cc * HW_ + qq]           = acc[mt][n][0];
            ob[(cc + 1) * HW_ + qq]     = acc[mt][n][1];
            ob[cc * HW_ + qq + 8]       = acc[mt][n][2];
            ob[(cc + 1) * HW_ + qq + 8] = acc[mt][n][3];
        }
    }
}

// ---------------- combine (fused accHT/lHT transpose):
// out[b,c,h,w] = yin + g*(accHT[b,c,w,h] + accW[b,c,h,w]) / (lHT[b,w,h] + lW[b,h,w])
__global__ void combine2_kernel(
    const float* __restrict__ yin, const float* __restrict__ accHT,
    const float* __restrict__ accW, const float* __restrict__ lHT,
    const float* __restrict__ lW, const float* __restrict__ gamma,
    float* __restrict__ out) {
    __shared__ float sH[32][33];
    __shared__ float sL[32][33];
    int bc = blockIdx.z;              // b*64 + c
    int b = bc >> 6;
    int h0 = blockIdx.y * 32, w0 = blockIdx.x * 32;
    int tx = threadIdx.x, ty = threadIdx.y;
    const float* aT = accHT + bc * HW_;
    const float* lT = lHT + b * HW_;
#pragma unroll
    for (int r = 0; r < 4; r++) {
        sH[ty + 8 * r][tx] = aT[(w0 + ty + 8 * r) * 128 + h0 + tx];
        sL[ty + 8 * r][tx] = lT[(w0 + ty + 8 * r) * 128 + h0 + tx];
    }
    __syncthreads();
    float g = *gamma;
    const float* yb = yin + bc * HW_;
    const float* wb = accW + bc * HW_;
    const float* lwb = lW + b * HW_;
    float* ob = out + bc * HW_;
#pragma unroll
    for (int r = 0; r < 4; r++) {
        int idx = (h0 + ty + 8 * r) * 128 + w0 + tx;
        float aH = sH[tx][ty + 8 * r];
        float lh = sL[tx][ty + 8 * r];
        ob[idx] = yb[idx] + g * (aH + wb[idx]) / (lh + lwb[idx]);
    }
}

// ---------------- pointwise 1x1 conv ----------------
__global__ void __launch_bounds__(256) pw_kernel(
    const float* __restrict__ in, const float* __restrict__ wpw,
    float* __restrict__ out) {
    __shared__ float ws[4096];
    int tid = threadIdx.x;
    for (int i = tid; i < 4096; i += 256) ws[i] = wpw[i];
    __syncthreads();
    int pix = blockIdx.x * 256 + tid;
    int b = pix >> 14, hw = pix & 16383;
    const float* ip = in + b * C_ * HW_ + hw;
    u64 yp[32];
#pragma unroll
    for (int c = 0; c < 32; c++)
        yp[c] = pack2(ip[(2 * c) * HW_], ip[(2 * c + 1) * HW_]);
#pragma unroll 1
    for (int o = 0; o < 64; o++)
        out[(b * 64 + o) * HW_ + hw] = dot64p(&ws[o * 64], yp);
}

extern "C" void kernel_launch(void* const* d_in, const int* in_sizes, int n_in,
                              void* d_out, int out_size) {
    const float* x    = (const float*)d_in[0];
    const float* w_dw = (const float*)d_in[1];
    const float* wq   = (const float*)d_in[2];
    const float* wk   = (const float*)d_in[3];
    const float* wv   = (const float*)d_in[4];
    const float* gam  = (const float*)d_in[5];
    const float* w_pw = (const float*)d_in[6];
    float* out = (float*)d_out;

    float *y, *y2, *q, *k, *v, *qT, *kT, *vT, *accW, *accHT, *lW, *lHT;
    cudaGetSymbolAddress((void**)&y, g_y);
    cudaGetSymbolAddress((void**)&y2, g_y2);
    cudaGetSymbolAddress((void**)&q, g_q);
    cudaGetSymbolAddress((void**)&k, g_k);
    cudaGetSymbolAddress((void**)&v, g_v);
    cudaGetSymbolAddress((void**)&qT, g_qT);
    cudaGetSymbolAddress((void**)&kT, g_kT);
    cudaGetSymbolAddress((void**)&vT, g_vT);
    cudaGetSymbolAddress((void**)&accW, g_accW);
    cudaGetSymbolAddress((void**)&accHT, g_accHT);
    cudaGetSymbolAddress((void**)&lW, g_lW);
    cudaGetSymbolAddress((void**)&lHT, g_lHT);

    const int attn_smem = ATTN_SMEM_FLOATS * 4;
    cudaFuncSetAttribute(attn_kernel,
                         cudaFuncAttributeMaxDynamicSharedMemorySize, attn_smem);

    dwconv_kernel<<<NELEM_ / 256, 256>>>(x, w_dw, y);

    const float* cin = y;
    float* cout = y2;
    for (int pass = 0; pass < 2; pass++) {
        qkv_kernel<<<NPIX_ / 256, 256>>>(cin, wq, wk, wv, q, k, v);
        transpose_kernel<<<dim3(4, 4, B_ * CQ_), dim3(32, 8)>>>(q, qT);
        transpose_kernel<<<dim3(4, 4, B_ * CQ_), dim3(32, 8)>>>(k, kT);
        transpose_kernel<<<dim3(4, 4, B_ * C_),  dim3(32, 8)>>>(v, vT);
        // W-direction (rows, no mask)
        attn_kernel<<<B_ * H_, 128, attn_smem>>>(q, k, v, accW, lW, 0);
        // H-direction (rows of transposed image, diagonal mask)
        attn_kernel<<<B_ * W_, 128, attn_smem>>>(qT, kT, vT, accHT, lHT, 1);
        // combine with fused back-transpose of accHT/lHT
        combine2_kernel<<<dim3(4, 4, B_ * C_), dim3(32, 8)>>>(
            cin, accHT, accW, lHT, lW, gam, cout);
        const float* t = cin; cin = cout; cout = (float*)t;
    }

    pw_kernel<<<NPIX_ / 256, 256>>>(cin, w_pw, out);
}